// round 1
// baseline (speedup 1.0000x reference)
#include <cuda_runtime.h>
#include <math.h>

#define B_  2
#define S_  2048
#define D_  1024
#define H_  16
#define HD_ 64
#define M_TOT (B_*S_)

#define BM 64
#define BN 64
#define BK 16

// Scratch (allocation-free: __device__ globals)
__device__ float g_q[B_*H_*S_*HD_];     // [B,H,S,HD] rope'd
__device__ float g_k[B_*H_*S_*HD_];
__device__ float g_v[B_*H_*S_*HD_];
__device__ float g_attn[(size_t)M_TOT*D_]; // attention output [B*S, D]
__device__ float g_cos[S_*32];
__device__ float g_sin[S_*32];

// ---------------------------------------------------------------------------
// RoPE tables: match numpy float32 pipeline (inv_freq computed in double,
// angle = fp32(t) * fp32(inv), cos/sin in fp32)
// ---------------------------------------------------------------------------
__global__ void rope_table_kernel() {
    int idx = blockIdx.x * blockDim.x + threadIdx.x;
    if (idx >= S_ * 32) return;
    int p = idx & 31;
    int t = idx >> 5;
    double inv = exp(-log(10000.0) * ((double)(2 * p) / 64.0));
    float ang = (float)t * (float)inv;
    g_cos[idx] = cosf(ang);
    g_sin[idx] = sinf(ang);
}

// ---------------------------------------------------------------------------
// QKV GEMM: Y = x @ W^T + b  (x:[M,K] row-major, W:[N,K] row-major)
// grid.z selects q/k/v. Epilogue applies RoPE (q,k) and writes [B,H,S,HD].
// Tile 64x64x16, 256 threads, 4x4 per thread.
// ---------------------------------------------------------------------------
__global__ __launch_bounds__(256) void qkv_kernel(
    const float* __restrict__ x,
    const float* __restrict__ Wq, const float* __restrict__ bq,
    const float* __restrict__ Wk, const float* __restrict__ bk,
    const float* __restrict__ Wv, const float* __restrict__ bv)
{
    __shared__ float As[BK][BM + 4];
    __shared__ float Bs[BK][BN + 4];

    int which = blockIdx.z;
    const float* W    = (which == 0) ? Wq : (which == 1) ? Wk : Wv;
    const float* bias = (which == 0) ? bq : (which == 1) ? bk : bv;
    float* out        = (which == 0) ? g_q : (which == 1) ? g_k : g_v;

    int tid = threadIdx.x;
    int tx = tid & 15, ty = tid >> 4;
    int row0 = blockIdx.y * BM, col0 = blockIdx.x * BN;
    int lr = tid >> 2;           // 0..63 tile row
    int lk = (tid & 3) << 2;     // 0,4,8,12

    const float* Aptr = x + (size_t)(row0 + lr) * D_ + lk;
    const float* Bptr = W + (size_t)(col0 + lr) * D_ + lk;

    float acc[4][4] = {};

    for (int k0 = 0; k0 < D_; k0 += BK) {
        float4 a = *(const float4*)(Aptr + k0);
        float4 b = *(const float4*)(Bptr + k0);
        As[lk + 0][lr] = a.x; As[lk + 1][lr] = a.y;
        As[lk + 2][lr] = a.z; As[lk + 3][lr] = a.w;
        Bs[lk + 0][lr] = b.x; Bs[lk + 1][lr] = b.y;
        Bs[lk + 2][lr] = b.z; Bs[lk + 3][lr] = b.w;
        __syncthreads();
#pragma unroll
        for (int kk = 0; kk < BK; kk++) {
            float4 av = *(const float4*)&As[kk][ty << 2];
            float4 bv = *(const float4*)&Bs[kk][tx << 2];
            float aa[4] = {av.x, av.y, av.z, av.w};
            float bb[4] = {bv.x, bv.y, bv.z, bv.w};
#pragma unroll
            for (int i = 0; i < 4; i++)
#pragma unroll
                for (int j = 0; j < 4; j++)
                    acc[i][j] += aa[i] * bb[j];
        }
        __syncthreads();
    }

    // epilogue: bias, rope (q,k), scatter into [B,H,S,HD]
    int n0 = col0 + (tx << 2);
    float b0 = bias[n0], b1 = bias[n0 + 1], b2 = bias[n0 + 2], b3 = bias[n0 + 3];
    int h_ = n0 >> 6;
    int d0 = n0 & 63;
    int p0 = d0 >> 1;
#pragma unroll
    for (int i = 0; i < 4; i++) {
        int m  = row0 + (ty << 2) + i;
        int bb_ = m >> 11;           // /S_
        int s_  = m & (S_ - 1);
        float v0 = acc[i][0] + b0, v1 = acc[i][1] + b1;
        float v2 = acc[i][2] + b2, v3 = acc[i][3] + b3;
        if (which < 2) {
            float c0 = g_cos[s_ * 32 + p0],     sn0 = g_sin[s_ * 32 + p0];
            float c1 = g_cos[s_ * 32 + p0 + 1], sn1 = g_sin[s_ * 32 + p0 + 1];
            float o0 = v0 * c0 - v1 * sn0;
            float o1 = v0 * sn0 + v1 * c0;
            float o2 = v2 * c1 - v3 * sn1;
            float o3 = v2 * sn1 + v3 * c1;
            v0 = o0; v1 = o1; v2 = o2; v3 = o3;
        }
        float* op = out + ((((size_t)(bb_ * H_ + h_) * S_ + s_) << 6) + d0);
        op[0] = v0; op[1] = v1; op[2] = v2; op[3] = v3;
    }
}

// ---------------------------------------------------------------------------
// Flash attention: per (q-tile 64, head, batch). Online softmax.
// Tiles 64x64, 256 threads, 4x4 scores per thread, HD=64 fully in smem.
// Skips k-tiles beyond min(causal bound, S - effective_len).
// ---------------------------------------------------------------------------
__global__ __launch_bounds__(256) void attn_kernel(const int* __restrict__ eff)
{
    extern __shared__ float sm[];
    float (*Qt)[68] = (float(*)[68])(sm);               // [kk][row]
    float (*Kt)[68] = (float(*)[68])(sm + 64 * 68);     // [kk][col]
    float (*Vs)[68] = (float(*)[68])(sm + 2 * 64 * 68); // [c][d]
    float (*Ps)[68] = (float(*)[68])(sm + 3 * 64 * 68); // [c][row]

    int qt = blockIdx.x, h = blockIdx.y, b = blockIdx.z;
    int q0 = qt * 64;
    int Slim = S_ - eff[b];                 // keys >= Slim are masked
    int kend = min(q0 + 64, Slim);          // exclusive bound on valid keys
    int nkt = (kend + 63) >> 6;             // >= 1 always (Slim > 1024)

    int tid = threadIdx.x;
    int tx = tid & 15, ty = tid >> 4;
    int lr16 = tid >> 4;                    // 0..15
    int lc4  = tid & 15;                    // float4 idx

    const float* qbase = g_q + (((size_t)(b * H_ + h) * S_ + q0) << 6);
    const float* kbase = g_k + (((size_t)(b * H_ + h) * S_) << 6);
    const float* vbase = g_v + (((size_t)(b * H_ + h) * S_) << 6);

    // load Q tile transposed: Qt[kk][row]
#pragma unroll
    for (int rr = 0; rr < 4; rr++) {
        int row = lr16 + rr * 16;
        float4 v = *(const float4*)(qbase + row * 64 + lc4 * 4);
        Qt[lc4 * 4 + 0][row] = v.x; Qt[lc4 * 4 + 1][row] = v.y;
        Qt[lc4 * 4 + 2][row] = v.z; Qt[lc4 * 4 + 3][row] = v.w;
    }

    float o[4][4] = {};
    float mi[4] = {-1e30f, -1e30f, -1e30f, -1e30f};
    float li[4] = {0.f, 0.f, 0.f, 0.f};

    for (int kt = 0; kt < nkt; kt++) {
        int c0 = kt * 64;
        __syncthreads();   // prior compute done before overwriting Kt/Vs
#pragma unroll
        for (int rr = 0; rr < 4; rr++) {
            int row = lr16 + rr * 16;
            float4 kv = *(const float4*)(kbase + (size_t)(c0 + row) * 64 + lc4 * 4);
            Kt[lc4 * 4 + 0][row] = kv.x; Kt[lc4 * 4 + 1][row] = kv.y;
            Kt[lc4 * 4 + 2][row] = kv.z; Kt[lc4 * 4 + 3][row] = kv.w;
            float4 vv = *(const float4*)(vbase + (size_t)(c0 + row) * 64 + lc4 * 4);
            *(float4*)&Vs[row][lc4 * 4] = vv;
        }
        __syncthreads();

        // S = Q K^T
        float s[4][4] = {};
#pragma unroll
        for (int kk = 0; kk < 64; kk++) {
            float4 av = *(const float4*)&Qt[kk][ty << 2];
            float4 bv = *(const float4*)&Kt[kk][tx << 2];
            float aa[4] = {av.x, av.y, av.z, av.w};
            float bb[4] = {bv.x, bv.y, bv.z, bv.w};
#pragma unroll
            for (int i = 0; i < 4; i++)
#pragma unroll
                for (int j = 0; j < 4; j++)
                    s[i][j] += aa[i] * bb[j];
        }

        // mask + scale + online softmax (row groups of 16 lanes)
        float p[4][4];
#pragma unroll
        for (int i = 0; i < 4; i++) {
            int gr = q0 + (ty << 2) + i;
            float rmax = -1e30f;
#pragma unroll
            for (int j = 0; j < 4; j++) {
                int gc = c0 + (tx << 2) + j;
                float sv = (gc > gr || gc >= Slim) ? -1e30f : s[i][j] * 0.125f;
                s[i][j] = sv;
                rmax = fmaxf(rmax, sv);
            }
#pragma unroll
            for (int msk = 8; msk >= 1; msk >>= 1)
                rmax = fmaxf(rmax, __shfl_xor_sync(0xffffffffu, rmax, msk));
            float mnew = fmaxf(mi[i], rmax);
            float scal = expf(mi[i] - mnew);
            float rs = 0.f;
#pragma unroll
            for (int j = 0; j < 4; j++) {
                float pv = expf(s[i][j] - mnew);
                p[i][j] = pv;
                rs += pv;
            }
#pragma unroll
            for (int msk = 8; msk >= 1; msk >>= 1)
                rs += __shfl_xor_sync(0xffffffffu, rs, msk);
            li[i] = li[i] * scal + rs;
            mi[i] = mnew;
#pragma unroll
            for (int j = 0; j < 4; j++) o[i][j] *= scal;
        }

        // P -> smem transposed: Ps[c][row]
#pragma unroll
        for (int i = 0; i < 4; i++)
#pragma unroll
            for (int j = 0; j < 4; j++)
                Ps[(tx << 2) + j][(ty << 2) + i] = p[i][j];
        __syncthreads();

        // O += P V
#pragma unroll
        for (int c = 0; c < 64; c++) {
            float4 av = *(const float4*)&Ps[c][ty << 2];
            float4 bv = *(const float4*)&Vs[c][tx << 2];
            float aa[4] = {av.x, av.y, av.z, av.w};
            float bb[4] = {bv.x, bv.y, bv.z, bv.w};
#pragma unroll
            for (int i = 0; i < 4; i++)
#pragma unroll
                for (int j = 0; j < 4; j++)
                    o[i][j] += aa[i] * bb[j];
        }
    }

    // finalize: divide by l, write [B,S,D]
#pragma unroll
    for (int i = 0; i < 4; i++) {
        int gr = q0 + (ty << 2) + i;
        float inv = 1.0f / li[i];
        float* op = g_attn + (size_t)(b * S_ + gr) * D_ + h * 64 + (tx << 2);
        op[0] = o[i][0] * inv; op[1] = o[i][1] * inv;
        op[2] = o[i][2] * inv; op[3] = o[i][3] * inv;
    }
}

// ---------------------------------------------------------------------------
// Output projection: d_out = g_attn @ Wo^T + bo
// ---------------------------------------------------------------------------
__global__ __launch_bounds__(256) void proj_kernel(
    const float* __restrict__ Wo, const float* __restrict__ bo,
    float* __restrict__ out)
{
    __shared__ float As[BK][BM + 4];
    __shared__ float Bs[BK][BN + 4];

    int tid = threadIdx.x;
    int tx = tid & 15, ty = tid >> 4;
    int row0 = blockIdx.y * BM, col0 = blockIdx.x * BN;
    int lr = tid >> 2;
    int lk = (tid & 3) << 2;

    const float* Aptr = g_attn + (size_t)(row0 + lr) * D_ + lk;
    const float* Bptr = Wo + (size_t)(col0 + lr) * D_ + lk;

    float acc[4][4] = {};

    for (int k0 = 0; k0 < D_; k0 += BK) {
        float4 a = *(const float4*)(Aptr + k0);
        float4 b = *(const float4*)(Bptr + k0);
        As[lk + 0][lr] = a.x; As[lk + 1][lr] = a.y;
        As[lk + 2][lr] = a.z; As[lk + 3][lr] = a.w;
        Bs[lk + 0][lr] = b.x; Bs[lk + 1][lr] = b.y;
        Bs[lk + 2][lr] = b.z; Bs[lk + 3][lr] = b.w;
        __syncthreads();
#pragma unroll
        for (int kk = 0; kk < BK; kk++) {
            float4 av = *(const float4*)&As[kk][ty << 2];
            float4 bv = *(const float4*)&Bs[kk][tx << 2];
            float aa[4] = {av.x, av.y, av.z, av.w};
            float bb[4] = {bv.x, bv.y, bv.z, bv.w};
#pragma unroll
            for (int i = 0; i < 4; i++)
#pragma unroll
                for (int j = 0; j < 4; j++)
                    acc[i][j] += aa[i] * bb[j];
        }
        __syncthreads();
    }

    int n0 = col0 + (tx << 2);
    float b0 = bo[n0], b1 = bo[n0 + 1], b2 = bo[n0 + 2], b3 = bo[n0 + 3];
#pragma unroll
    for (int i = 0; i < 4; i++) {
        int m = row0 + (ty << 2) + i;
        float* op = out + (size_t)m * D_ + n0;
        op[0] = acc[i][0] + b0;
        op[1] = acc[i][1] + b1;
        op[2] = acc[i][2] + b2;
        op[3] = acc[i][3] + b3;
    }
}

// ---------------------------------------------------------------------------
extern "C" void kernel_launch(void* const* d_in, const int* in_sizes, int n_in,
                              void* d_out, int out_size)
{
    const float* x   = (const float*)d_in[0];
    const int*   eff = (const int*)  d_in[1];
    const float* Wq  = (const float*)d_in[2];
    const float* bq  = (const float*)d_in[3];
    const float* Wk  = (const float*)d_in[4];
    const float* bk  = (const float*)d_in[5];
    const float* Wv  = (const float*)d_in[6];
    const float* bv  = (const float*)d_in[7];
    const float* Wo  = (const float*)d_in[8];
    const float* bo  = (const float*)d_in[9];
    float* out = (float*)d_out;

    static bool attr_set = false;
    if (!attr_set) {
        cudaFuncSetAttribute(attn_kernel,
                             cudaFuncAttributeMaxDynamicSharedMemorySize,
                             4 * 64 * 68 * (int)sizeof(float));
        attr_set = true;
    }

    rope_table_kernel<<<(S_ * 32 + 255) / 256, 256>>>();

    dim3 gq(D_ / BN, M_TOT / BM, 3);
    qkv_kernel<<<gq, 256>>>(x, Wq, bq, Wk, bk, Wv, bv);

    dim3 ga(S_ / 64, H_, B_);
    attn_kernel<<<ga, 256, 4 * 64 * 68 * sizeof(float)>>>(eff);

    dim3 gp(D_ / BN, M_TOT / BM);
    proj_kernel<<<gp, 256>>>(Wo, bo, out);
}

// round 2
// speedup vs baseline: 2.9865x; 2.9865x over previous
#include <cuda_runtime.h>
#include <math.h>
#include <stdint.h>

#define B_  2
#define S_  2048
#define D_  1024
#define H_  16
#define M_TOT (B_*S_)

// Scratch (allocation-free: __device__ globals)
__device__ float g_q[B_*H_*S_*64];      // [B,H,S,64] rope'd
__device__ float g_k[B_*H_*S_*64];
__device__ float g_v[B_*H_*S_*64];
__device__ float g_attn[(size_t)M_TOT*D_];
__device__ float g_cos[S_*32];
__device__ float g_sin[S_*32];

// ---------------------------------------------------------------------------
// helpers: tf32 convert, ldmatrix, mma
// ---------------------------------------------------------------------------
__device__ __forceinline__ uint32_t f2tf(float x){
    uint32_t u; asm("cvt.rna.tf32.f32 %0, %1;" : "=r"(u) : "f"(x)); return u;
}
__device__ __forceinline__ float4 cvt4(float4 v){
    float4 r;
    r.x=__uint_as_float(f2tf(v.x)); r.y=__uint_as_float(f2tf(v.y));
    r.z=__uint_as_float(f2tf(v.z)); r.w=__uint_as_float(f2tf(v.w));
    return r;
}
__device__ __forceinline__ void ldsm4(uint32_t* r, uint32_t addr){
    asm volatile("ldmatrix.sync.aligned.m8n8.x4.shared.b16 {%0,%1,%2,%3}, [%4];"
        : "=r"(r[0]),"=r"(r[1]),"=r"(r[2]),"=r"(r[3]) : "r"(addr));
}
__device__ __forceinline__ void mma8(float* c, const uint32_t* a, uint32_t b0, uint32_t b1){
    asm volatile("mma.sync.aligned.m16n8k8.row.col.f32.tf32.tf32.f32 "
        "{%0,%1,%2,%3},{%4,%5,%6,%7},{%8,%9},{%0,%1,%2,%3};"
        : "+f"(c[0]),"+f"(c[1]),"+f"(c[2]),"+f"(c[3])
        : "r"(a[0]),"r"(a[1]),"r"(a[2]),"r"(a[3]),"r"(b0),"r"(b1));
}
// XOR-swizzled [row][word] layouts (16B-chunk swizzle; conflict-free LDSM)
__device__ __forceinline__ int swz32(int r,int w){ return r*32 + ((((w>>2)^(r&7))<<2)|(w&3)); }
__device__ __forceinline__ int swz64(int r,int w){ return r*64 + ((((w>>2)^(r&7))<<2)|(w&3)); }

// ---------------------------------------------------------------------------
// RoPE tables (match numpy fp32 pipeline)
// ---------------------------------------------------------------------------
__global__ void rope_table_kernel() {
    int idx = blockIdx.x * blockDim.x + threadIdx.x;
    if (idx >= S_ * 32) return;
    int p = idx & 31;
    int t = idx >> 5;
    double inv = exp(-log(10000.0) * ((double)(2 * p) / 64.0));
    float ang = (float)t * (float)inv;
    g_cos[idx] = cosf(ang);
    g_sin[idx] = sinf(ang);
}

// ---------------------------------------------------------------------------
// TF32 tensor-core GEMM: Y = A @ W^T + b.  A:[4096,1024] row, W:[N,K] row.
// Block 128x128, BK=32, 256 threads, 8 warps (2M x 4N), warp tile 64x32.
// IS_QKV: grid.z selects q/k/v; epilogue applies RoPE and scatters [B,H,S,64].
// ---------------------------------------------------------------------------
template<bool IS_QKV>
__global__ __launch_bounds__(256,1) void gemm_tc(
    const float* __restrict__ Ain,
    const float* __restrict__ Wq, const float* __restrict__ bq,
    const float* __restrict__ Wk, const float* __restrict__ bk,
    const float* __restrict__ Wv, const float* __restrict__ bv,
    float* __restrict__ outp)
{
    __shared__ float As[128*32];
    __shared__ float Bs[128*32];

    const float* A;
    const float* W;
    const float* bias;
    float* out;
    int which = 0;
    if (IS_QKV) {
        A = Ain;
        which = blockIdx.z;
        W    = (which==0) ? Wq : (which==1) ? Wk : Wv;
        bias = (which==0) ? bq : (which==1) ? bk : bv;
        out  = (which==0) ? g_q : (which==1) ? g_k : g_v;
    } else {
        A = g_attn; W = Wq; bias = bq; out = outp;
    }

    int tid = threadIdx.x, lane = tid & 31, warp = tid >> 5;
    int wm = (warp & 1) * 64, wn = (warp >> 1) * 32;
    int lm = lane >> 3, lr = lane & 7;
    int row0 = blockIdx.y * 128, col0 = blockIdx.x * 128;

    uint32_t aB = (uint32_t)__cvta_generic_to_shared(As);
    uint32_t bB = (uint32_t)__cvta_generic_to_shared(Bs);

    int ldr = tid >> 3;          // 0..31
    int ldc = (tid & 7) * 4;     // word
    const float* aP = A + (size_t)(row0 + ldr) * D_ + ldc;
    const float* bP = W + (size_t)(col0 + ldr) * D_ + ldc;

    float acc[4][4][4];
#pragma unroll
    for (int i=0;i<4;i++)
#pragma unroll
        for (int j=0;j<4;j++)
#pragma unroll
            for (int k=0;k<4;k++) acc[i][j][k]=0.f;

    for (int k0 = 0; k0 < D_; k0 += 32) {
        float4 pa[4], pb[4];
#pragma unroll
        for (int it = 0; it < 4; it++) {
            pa[it] = *(const float4*)(aP + (size_t)it*32*D_ + k0);
            pb[it] = *(const float4*)(bP + (size_t)it*32*D_ + k0);
        }
        __syncthreads();
#pragma unroll
        for (int it = 0; it < 4; it++) {
            *(float4*)&As[swz32(ldr + it*32, ldc)] = cvt4(pa[it]);
            *(float4*)&Bs[swz32(ldr + it*32, ldc)] = cvt4(pb[it]);
        }
        __syncthreads();
#pragma unroll
        for (int ks = 0; ks < 32; ks += 8) {
            uint32_t af[4][4];
#pragma unroll
            for (int mt = 0; mt < 4; mt++)
                ldsm4(af[mt], aB + 4*swz32(wm + mt*16 + (lm&1)*8 + lr, ks + (lm>>1)*4));
            uint32_t bf[4][2];
#pragma unroll
            for (int p = 0; p < 2; p++) {
                uint32_t t[4];
                ldsm4(t, bB + 4*swz32(wn + p*16 + (lm>>1)*8 + lr, ks + (lm&1)*4));
                bf[2*p][0]=t[0]; bf[2*p][1]=t[1]; bf[2*p+1][0]=t[2]; bf[2*p+1][1]=t[3];
            }
#pragma unroll
            for (int mt = 0; mt < 4; mt++)
#pragma unroll
                for (int nt = 0; nt < 4; nt++)
                    mma8(acc[mt][nt], af[mt], bf[nt][0], bf[nt][1]);
        }
    }

    int g = lane >> 2, tig = lane & 3;
#pragma unroll
    for (int mt = 0; mt < 4; mt++) {
#pragma unroll
        for (int nt = 0; nt < 4; nt++) {
            int ncol = col0 + wn + nt*8 + tig*2;
            float b0 = bias[ncol], b1 = bias[ncol+1];
#pragma unroll
            for (int h2 = 0; h2 < 2; h2++) {
                int m = row0 + wm + mt*16 + g + h2*8;
                float v0 = acc[mt][nt][h2*2]   + b0;
                float v1 = acc[mt][nt][h2*2+1] + b1;
                if (IS_QKV) {
                    int s_ = m & (S_-1);
                    int hh = ncol >> 6, d0 = ncol & 63;
                    if (which < 2) {
                        int p = d0 >> 1;
                        float c = g_cos[s_*32+p], sn = g_sin[s_*32+p];
                        float o0 = v0*c - v1*sn;
                        float o1 = v0*sn + v1*c;
                        v0 = o0; v1 = o1;
                    }
                    int bb = m >> 11;
                    float2* op = (float2*)(out + (((size_t)(bb*H_ + hh)*S_ + s_)<<6) + d0);
                    *op = make_float2(v0, v1);
                } else {
                    float2* op = (float2*)(out + (size_t)m*D_ + ncol);
                    *op = make_float2(v0, v1);
                }
            }
        }
    }
}

// ---------------------------------------------------------------------------
// TF32 flash attention: q-tile 128, k-tile 64, 8 warps x 16 q-rows each.
// Warp-local softmax (rows never cross warps); P is warp-private in smem.
// ---------------------------------------------------------------------------
__global__ __launch_bounds__(256,1) void attn_tc(const int* __restrict__ eff)
{
    extern __shared__ float sm[];
    float* Qs = sm;                               // swz64, 128x64
    float* Ks = sm + 128*64;                      // swz64, 64x64
    float* Ps = sm + 128*64 + 64*64;              // swz64, 128x64
    float* Vs = sm + 128*64 + 64*64 + 128*64;     // [c][n], stride 72

    int tid = threadIdx.x, lane = tid & 31, warp = tid >> 5;
    int g = lane >> 2, tig = lane & 3, lm = lane >> 3, lr = lane & 7;
    int q0 = blockIdx.x * 128, h = blockIdx.y, b = blockIdx.z;
    int wq = warp * 16;

    const float* qb = g_q + (((size_t)(b*H_+h)*S_ + q0) << 6);
    const float* kb = g_k + (((size_t)(b*H_+h)*S_) << 6);
    const float* vb = g_v + (((size_t)(b*H_+h)*S_) << 6);

    uint32_t QsB = (uint32_t)__cvta_generic_to_shared(Qs);
    uint32_t KsB = (uint32_t)__cvta_generic_to_shared(Ks);
    uint32_t PsB = (uint32_t)__cvta_generic_to_shared(Ps);

    int lrow = tid >> 4;         // 0..15
    int lcol = (tid & 15) * 4;   // word
#pragma unroll
    for (int it = 0; it < 8; it++) {
        int r = lrow + it*16;
        float4 v = *(const float4*)(qb + r*64 + lcol);
        *(float4*)&Qs[swz64(r, lcol)] = cvt4(v);
    }

    int Slim = S_ - eff[b];
    int kend = min(q0 + 128, Slim);
    int nkt = (kend + 63) >> 6;

    float o[8][4];
#pragma unroll
    for (int i=0;i<8;i++)
#pragma unroll
        for (int j=0;j<4;j++) o[i][j]=0.f;
    float mi0=-1e30f, mi1=-1e30f, li0=0.f, li1=0.f;

    int r0g = q0 + wq + g;
    int r1g = r0g + 8;

    for (int kt = 0; kt < nkt; kt++) {
        int c0 = kt * 64;
        __syncthreads();                     // prior PV reads of Ks/Vs done
#pragma unroll
        for (int it = 0; it < 4; it++) {
            int r = lrow + it*16;
            float4 kv = *(const float4*)(kb + (size_t)(c0+r)*64 + lcol);
            *(float4*)&Ks[swz64(r, lcol)] = cvt4(kv);
            float4 vv = *(const float4*)(vb + (size_t)(c0+r)*64 + lcol);
            *(float4*)&Vs[r*72 + lcol] = cvt4(vv);
        }
        __syncthreads();

        if (c0 <= q0 + wq + 15) {            // causal: skip fully-masked tiles
            // S = Q K^T
            float s[8][4];
#pragma unroll
            for (int i=0;i<8;i++)
#pragma unroll
                for (int j=0;j<4;j++) s[i][j]=0.f;
#pragma unroll
            for (int ks = 0; ks < 64; ks += 8) {
                uint32_t af[4];
                ldsm4(af, QsB + 4*swz64(wq + (lm&1)*8 + lr, ks + (lm>>1)*4));
#pragma unroll
                for (int p = 0; p < 4; p++) {
                    uint32_t t[4];
                    ldsm4(t, KsB + 4*swz64(p*16 + (lm>>1)*8 + lr, ks + (lm&1)*4));
                    mma8(s[2*p],   af, t[0], t[1]);
                    mma8(s[2*p+1], af, t[2], t[3]);
                }
            }
            // mask + scale + row max
            float rm0=-1e30f, rm1=-1e30f;
#pragma unroll
            for (int nt = 0; nt < 8; nt++) {
                int c = c0 + nt*8 + tig*2;
                float v;
                v = (c   > r0g || c   >= Slim) ? -1e30f : s[nt][0]*0.125f; s[nt][0]=v; rm0=fmaxf(rm0,v);
                v = (c+1 > r0g || c+1 >= Slim) ? -1e30f : s[nt][1]*0.125f; s[nt][1]=v; rm0=fmaxf(rm0,v);
                v = (c   > r1g || c   >= Slim) ? -1e30f : s[nt][2]*0.125f; s[nt][2]=v; rm1=fmaxf(rm1,v);
                v = (c+1 > r1g || c+1 >= Slim) ? -1e30f : s[nt][3]*0.125f; s[nt][3]=v; rm1=fmaxf(rm1,v);
            }
            rm0 = fmaxf(rm0, __shfl_xor_sync(0xffffffffu, rm0, 1));
            rm0 = fmaxf(rm0, __shfl_xor_sync(0xffffffffu, rm0, 2));
            rm1 = fmaxf(rm1, __shfl_xor_sync(0xffffffffu, rm1, 1));
            rm1 = fmaxf(rm1, __shfl_xor_sync(0xffffffffu, rm1, 2));
            float mn0 = fmaxf(mi0, rm0), mn1 = fmaxf(mi1, rm1);
            float sc0 = __expf(mi0 - mn0), sc1 = __expf(mi1 - mn1);
            float rs0 = 0.f, rs1 = 0.f;
#pragma unroll
            for (int nt = 0; nt < 8; nt++) {
                float p00 = __expf(s[nt][0]-mn0), p01 = __expf(s[nt][1]-mn0);
                float p10 = __expf(s[nt][2]-mn1), p11 = __expf(s[nt][3]-mn1);
                rs0 += p00 + p01; rs1 += p10 + p11;
                int w = nt*8 + tig*2;
                *(float2*)&Ps[swz64(wq+g,   w)] =
                    make_float2(__uint_as_float(f2tf(p00)), __uint_as_float(f2tf(p01)));
                *(float2*)&Ps[swz64(wq+g+8, w)] =
                    make_float2(__uint_as_float(f2tf(p10)), __uint_as_float(f2tf(p11)));
                o[nt][0]*=sc0; o[nt][1]*=sc0; o[nt][2]*=sc1; o[nt][3]*=sc1;
            }
            rs0 += __shfl_xor_sync(0xffffffffu, rs0, 1);
            rs0 += __shfl_xor_sync(0xffffffffu, rs0, 2);
            rs1 += __shfl_xor_sync(0xffffffffu, rs1, 1);
            rs1 += __shfl_xor_sync(0xffffffffu, rs1, 2);
            li0 = li0*sc0 + rs0; li1 = li1*sc1 + rs1;
            mi0 = mn0; mi1 = mn1;
            __syncwarp();                    // P visible within warp

            // O += P V   (P warp-private rows; V shared, stable until next sync)
#pragma unroll
            for (int cs = 0; cs < 64; cs += 8) {
                uint32_t pf[4];
                ldsm4(pf, PsB + 4*swz64(wq + (lm&1)*8 + lr, cs + (lm>>1)*4));
#pragma unroll
                for (int nt = 0; nt < 8; nt++) {
                    uint32_t b0 = __float_as_uint(Vs[(cs+tig)*72   + nt*8 + g]);
                    uint32_t b1 = __float_as_uint(Vs[(cs+tig+4)*72 + nt*8 + g]);
                    mma8(o[nt], pf, b0, b1);
                }
            }
        }
    }

    float inv0 = 1.0f / li0, inv1 = 1.0f / li1;
#pragma unroll
    for (int nt = 0; nt < 8; nt++) {
        int col = h*64 + nt*8 + tig*2;
        *(float2*)&g_attn[(size_t)(b*S_ + r0g)*D_ + col] =
            make_float2(o[nt][0]*inv0, o[nt][1]*inv0);
        *(float2*)&g_attn[(size_t)(b*S_ + r1g)*D_ + col] =
            make_float2(o[nt][2]*inv1, o[nt][3]*inv1);
    }
}

// ---------------------------------------------------------------------------
extern "C" void kernel_launch(void* const* d_in, const int* in_sizes, int n_in,
                              void* d_out, int out_size)
{
    const float* x   = (const float*)d_in[0];
    const int*   eff = (const int*)  d_in[1];
    const float* Wq  = (const float*)d_in[2];
    const float* bq  = (const float*)d_in[3];
    const float* Wk  = (const float*)d_in[4];
    const float* bk  = (const float*)d_in[5];
    const float* Wv  = (const float*)d_in[6];
    const float* bv  = (const float*)d_in[7];
    const float* Wo  = (const float*)d_in[8];
    const float* bo  = (const float*)d_in[9];
    float* out = (float*)d_out;

    static bool attr_set = false;
    if (!attr_set) {
        cudaFuncSetAttribute(attn_tc,
                             cudaFuncAttributeMaxDynamicSharedMemorySize,
                             (128*64 + 64*64 + 128*64 + 64*72) * (int)sizeof(float));
        attr_set = true;
    }

    rope_table_kernel<<<(S_*32 + 255)/256, 256>>>();

    dim3 gq(D_/128, M_TOT/128, 3);
    gemm_tc<true><<<gq, 256>>>(x, Wq, bq, Wk, bk, Wv, bv, nullptr);

    dim3 ga(S_/128, H_, B_);
    attn_tc<<<ga, 256, (128*64 + 64*64 + 128*64 + 64*72)*sizeof(float)>>>(eff);

    dim3 gp(D_/128, M_TOT/128, 1);
    gemm_tc<false><<<gp, 256>>>(nullptr, Wo, bo, nullptr, nullptr, nullptr, nullptr, out);
}

// round 3
// speedup vs baseline: 4.1816x; 1.4001x over previous
#include <cuda_runtime.h>
#include <math.h>
#include <stdint.h>

#define B_  2
#define S_  2048
#define D_  1024
#define H_  16
#define M_TOT (B_*S_)

// Scratch (allocation-free: __device__ globals)
__device__ float g_x[(size_t)M_TOT*D_];   // tf32-rounded x
__device__ float g_wq[D_*D_];
__device__ float g_wk[D_*D_];
__device__ float g_wv[D_*D_];
__device__ float g_wo[D_*D_];
__device__ float g_q[B_*H_*S_*64];        // [B,H,S,64] rope'd, tf32-rounded
__device__ float g_k[B_*H_*S_*64];
__device__ float g_v[B_*H_*S_*64];
__device__ float g_attn[(size_t)M_TOT*D_]; // tf32-rounded attn output
__device__ float g_cos[S_*32];
__device__ float g_sin[S_*32];

// ---------------------------------------------------------------------------
// helpers
// ---------------------------------------------------------------------------
__device__ __forceinline__ uint32_t f2tf(float x){
    uint32_t u; asm("cvt.rna.tf32.f32 %0, %1;" : "=r"(u) : "f"(x)); return u;
}
__device__ __forceinline__ float4 cvt4(float4 v){
    float4 r;
    r.x=__uint_as_float(f2tf(v.x)); r.y=__uint_as_float(f2tf(v.y));
    r.z=__uint_as_float(f2tf(v.z)); r.w=__uint_as_float(f2tf(v.w));
    return r;
}
__device__ __forceinline__ void ldsm4(uint32_t* r, uint32_t addr){
    asm volatile("ldmatrix.sync.aligned.m8n8.x4.shared.b16 {%0,%1,%2,%3}, [%4];"
        : "=r"(r[0]),"=r"(r[1]),"=r"(r[2]),"=r"(r[3]) : "r"(addr));
}
__device__ __forceinline__ void mma8(float* c, const uint32_t* a, uint32_t b0, uint32_t b1){
    asm volatile("mma.sync.aligned.m16n8k8.row.col.f32.tf32.tf32.f32 "
        "{%0,%1,%2,%3},{%4,%5,%6,%7},{%8,%9},{%0,%1,%2,%3};"
        : "+f"(c[0]),"+f"(c[1]),"+f"(c[2]),"+f"(c[3])
        : "r"(a[0]),"r"(a[1]),"r"(a[2]),"r"(a[3]),"r"(b0),"r"(b1));
}
__device__ __forceinline__ void cpa16(uint32_t dst, const float* src){
    asm volatile("cp.async.cg.shared.global [%0], [%1], 16;" :: "r"(dst), "l"(src));
}
#define CP_COMMIT() asm volatile("cp.async.commit_group;")
#define CP_WAIT(n)  asm volatile("cp.async.wait_group %0;"::"n"(n))

// XOR-swizzled [row][word] layouts (16B-chunk swizzle; conflict-free LDSM)
__device__ __forceinline__ int swz32(int r,int w){ return r*32 + ((((w>>2)^(r&7))<<2)|(w&3)); }
__device__ __forceinline__ int swz64(int r,int w){ return r*64 + ((((w>>2)^(r&7))<<2)|(w&3)); }

// ---------------------------------------------------------------------------
// RoPE tables (match numpy fp32 pipeline)
// ---------------------------------------------------------------------------
__global__ void rope_table_kernel() {
    int idx = blockIdx.x * blockDim.x + threadIdx.x;
    if (idx >= S_ * 32) return;
    int p = idx & 31;
    int t = idx >> 5;
    double inv = exp(-log(10000.0) * ((double)(2 * p) / 64.0));
    float ang = (float)t * (float)inv;
    g_cos[idx] = cosf(ang);
    g_sin[idx] = sinf(ang);
}

// ---------------------------------------------------------------------------
// prep: tf32-round x and the four weight matrices into device scratch
// ---------------------------------------------------------------------------
#define NXF4 ((M_TOT*D_)/4)
#define NWF4 ((D_*D_)/4)
__global__ void prep_kernel(const float* __restrict__ x,
                            const float* __restrict__ Wq, const float* __restrict__ Wk,
                            const float* __restrict__ Wv, const float* __restrict__ Wo)
{
    int i = blockIdx.x * blockDim.x + threadIdx.x;
    if (i < NXF4) { ((float4*)g_x)[i] = cvt4(((const float4*)x)[i]); return; }
    i -= NXF4;
    if (i < NWF4) { ((float4*)g_wq)[i] = cvt4(((const float4*)Wq)[i]); return; }
    i -= NWF4;
    if (i < NWF4) { ((float4*)g_wk)[i] = cvt4(((const float4*)Wk)[i]); return; }
    i -= NWF4;
    if (i < NWF4) { ((float4*)g_wv)[i] = cvt4(((const float4*)Wv)[i]); return; }
    i -= NWF4;
    if (i < NWF4) { ((float4*)g_wo)[i] = cvt4(((const float4*)Wo)[i]); return; }
}

// ---------------------------------------------------------------------------
// TF32 tensor-core GEMM, cp.async 3-stage pipeline.
// Y = A @ W^T + b. Block 128x128, BK=32, 256 threads, warp tile 64x32.
// Operands are pre-rounded tf32 -> raw 16B async copies, no convert in path.
// ---------------------------------------------------------------------------
#define GSTG 3
#define GTILE (128*32)

template<bool IS_QKV>
__global__ __launch_bounds__(256,2) void gemm_tc(
    const float* __restrict__ bq, const float* __restrict__ bk,
    const float* __restrict__ bv, float* __restrict__ outp)
{
    extern __shared__ float sm[];
    float* As = sm;                 // [GSTG][128*32]
    float* Bs = sm + GSTG*GTILE;

    const float* A; const float* W; const float* bias; float* out;
    int which = 0;
    if (IS_QKV) {
        which = blockIdx.z;
        A = g_x;
        W    = (which==0) ? g_wq : (which==1) ? g_wk : g_wv;
        bias = (which==0) ? bq   : (which==1) ? bk   : bv;
        out  = (which==0) ? g_q  : (which==1) ? g_k  : g_v;
    } else {
        A = g_attn; W = g_wo; bias = bq; out = outp;
    }

    int tid = threadIdx.x, lane = tid & 31, warp = tid >> 5;
    int wm = (warp & 1) * 64, wn = (warp >> 1) * 32;
    int lm = lane >> 3, lr = lane & 7;
    int row0 = blockIdx.y * 128, col0 = blockIdx.x * 128;

    uint32_t aB = (uint32_t)__cvta_generic_to_shared(As);
    uint32_t bB = (uint32_t)__cvta_generic_to_shared(Bs);

    int ldr = tid >> 3;          // 0..31
    int ldc = (tid & 7) * 4;     // word
    int swo = swz32(ldr, ldc);   // swizzle offset for row ldr (row&7 invariant under +32)
    const float* aP = A + (size_t)(row0 + ldr) * D_ + ldc;
    const float* bP = W + (size_t)(col0 + ldr) * D_ + ldc;

    float acc[4][4][4];
#pragma unroll
    for (int i=0;i<4;i++)
#pragma unroll
        for (int j=0;j<4;j++)
#pragma unroll
            for (int k=0;k<4;k++) acc[i][j][k]=0.f;

    const int NT = D_/32;

    // prologue: fill 3 stages
#pragma unroll
    for (int s = 0; s < GSTG; s++) {
        uint32_t ab = aB + (uint32_t)(s*GTILE*4);
        uint32_t bb = bB + (uint32_t)(s*GTILE*4);
        int k0 = s*32;
#pragma unroll
        for (int it = 0; it < 4; it++) {
            cpa16(ab + 4*(swo + it*32*32), aP + (size_t)it*32*D_ + k0);
            cpa16(bb + 4*(swo + it*32*32), bP + (size_t)it*32*D_ + k0);
        }
        CP_COMMIT();
    }

    for (int kt = 0; kt < NT; kt++) {
        CP_WAIT(2);
        __syncthreads();

        int buf = kt % GSTG;
        uint32_t ab = aB + (uint32_t)(buf*GTILE*4);
        uint32_t bb = bB + (uint32_t)(buf*GTILE*4);
#pragma unroll
        for (int ks = 0; ks < 32; ks += 8) {
            uint32_t af[4][4];
#pragma unroll
            for (int mt = 0; mt < 4; mt++)
                ldsm4(af[mt], ab + 4*swz32(wm + mt*16 + (lm&1)*8 + lr, ks + (lm>>1)*4));
            uint32_t bf[4][2];
#pragma unroll
            for (int p = 0; p < 2; p++) {
                uint32_t t[4];
                ldsm4(t, bb + 4*swz32(wn + p*16 + (lm>>1)*8 + lr, ks + (lm&1)*4));
                bf[2*p][0]=t[0]; bf[2*p][1]=t[1]; bf[2*p+1][0]=t[2]; bf[2*p+1][1]=t[3];
            }
#pragma unroll
            for (int mt = 0; mt < 4; mt++)
#pragma unroll
                for (int nt = 0; nt < 4; nt++)
                    mma8(acc[mt][nt], af[mt], bf[nt][0], bf[nt][1]);
        }
        __syncthreads();

        if (kt + GSTG < NT) {
            int k0 = (kt + GSTG)*32;
#pragma unroll
            for (int it = 0; it < 4; it++) {
                cpa16(ab + 4*(swo + it*32*32), aP + (size_t)it*32*D_ + k0);
                cpa16(bb + 4*(swo + it*32*32), bP + (size_t)it*32*D_ + k0);
            }
        }
        CP_COMMIT();
    }

    int g = lane >> 2, tig = lane & 3;
#pragma unroll
    for (int mt = 0; mt < 4; mt++) {
#pragma unroll
        for (int nt = 0; nt < 4; nt++) {
            int ncol = col0 + wn + nt*8 + tig*2;
            float b0 = bias[ncol], b1 = bias[ncol+1];
#pragma unroll
            for (int h2 = 0; h2 < 2; h2++) {
                int m = row0 + wm + mt*16 + g + h2*8;
                float v0 = acc[mt][nt][h2*2]   + b0;
                float v1 = acc[mt][nt][h2*2+1] + b1;
                if (IS_QKV) {
                    int s_ = m & (S_-1);
                    int hh = ncol >> 6, d0 = ncol & 63;
                    if (which < 2) {
                        int p = d0 >> 1;
                        float c = g_cos[s_*32+p], sn = g_sin[s_*32+p];
                        float o0 = v0*c - v1*sn;
                        float o1 = v0*sn + v1*c;
                        v0 = o0; v1 = o1;
                    }
                    // pre-round for the attention MMA consumers (same values
                    // as R2's convert-at-smem-store)
                    v0 = __uint_as_float(f2tf(v0));
                    v1 = __uint_as_float(f2tf(v1));
                    int bb_ = m >> 11;
                    float2* op = (float2*)(out + (((size_t)(bb_*H_ + hh)*S_ + s_)<<6) + d0);
                    *op = make_float2(v0, v1);
                } else {
                    float2* op = (float2*)(out + (size_t)m*D_ + ncol);
                    *op = make_float2(v0, v1);
                }
            }
        }
    }
}

// ---------------------------------------------------------------------------
// TF32 flash attention, cp.async double-buffered K/V.
// q-tile 128, k-tile 64, 8 warps x 16 q-rows each. Warp-local softmax.
// ---------------------------------------------------------------------------
#define KVTILE (64*64 + 64*72)   // Ks(swz64) + Vs(stride 72)

__global__ __launch_bounds__(256,1) void attn_tc(const int* __restrict__ eff)
{
    extern __shared__ float sm[];
    float* Qs  = sm;                       // swz64, 128x64
    float* Ps  = sm + 128*64;              // swz64, 128x64
    float* KV0 = sm + 2*128*64;            // [2] stages
    // per stage: Ks at +0 (swz64 64x64), Vs at +64*64 ([c][n] stride 72)

    int tid = threadIdx.x, lane = tid & 31, warp = tid >> 5;
    int g = lane >> 2, tig = lane & 3, lm = lane >> 3, lr = lane & 7;
    int q0 = blockIdx.x * 128, h = blockIdx.y, b = blockIdx.z;
    int wq = warp * 16;

    const float* qb = g_q + (((size_t)(b*H_+h)*S_ + q0) << 6);
    const float* kb = g_k + (((size_t)(b*H_+h)*S_) << 6);
    const float* vb = g_v + (((size_t)(b*H_+h)*S_) << 6);

    uint32_t QsB = (uint32_t)__cvta_generic_to_shared(Qs);
    uint32_t PsB = (uint32_t)__cvta_generic_to_shared(Ps);
    uint32_t KVB = (uint32_t)__cvta_generic_to_shared(KV0);

    int lrow = tid >> 4;         // 0..15
    int lcol = (tid & 15) * 4;   // word
    int swoQ = swz64(lrow, lcol);

    int Slim = S_ - eff[b];
    int kend = min(q0 + 128, Slim);
    int nkt = (kend + 63) >> 6;

    // group 0: Q tile + KV tile 0
#pragma unroll
    for (int it = 0; it < 8; it++)
        cpa16(QsB + 4*(swoQ + it*16*64), qb + (it*16 + lrow)*64 + lcol);
#pragma unroll
    for (int it = 0; it < 4; it++) {
        int r = lrow + it*16;
        cpa16(KVB + 4*(swoQ + it*16*64), kb + (size_t)r*64 + lcol);
        cpa16(KVB + 4*(64*64 + r*72 + lcol), vb + (size_t)r*64 + lcol);
    }
    CP_COMMIT();

    float o[8][4];
#pragma unroll
    for (int i=0;i<8;i++)
#pragma unroll
        for (int j=0;j<4;j++) o[i][j]=0.f;
    float mi0=-1e30f, mi1=-1e30f, li0=0.f, li1=0.f;

    int r0g = q0 + wq + g;
    int r1g = r0g + 8;

    for (int kt = 0; kt < nkt; kt++) {
        // prefetch next KV tile into the other buffer
        if (kt + 1 < nkt) {
            uint32_t kvb = KVB + (uint32_t)(((kt+1)&1) * KVTILE * 4);
            int c0n = (kt+1) * 64;
#pragma unroll
            for (int it = 0; it < 4; it++) {
                int r = lrow + it*16;
                cpa16(kvb + 4*(swoQ + it*16*64), kb + (size_t)(c0n+r)*64 + lcol);
                cpa16(kvb + 4*(64*64 + r*72 + lcol), vb + (size_t)(c0n+r)*64 + lcol);
            }
        }
        CP_COMMIT();
        CP_WAIT(1);
        __syncthreads();

        int c0 = kt * 64;
        uint32_t KsB = KVB + (uint32_t)((kt&1) * KVTILE * 4);
        const float* Vs = KV0 + (kt&1)*KVTILE + 64*64;

        if (c0 <= q0 + wq + 15) {            // causal: skip fully-masked tiles
            // S = Q K^T
            float s[8][4];
#pragma unroll
            for (int i=0;i<8;i++)
#pragma unroll
                for (int j=0;j<4;j++) s[i][j]=0.f;
#pragma unroll
            for (int ks = 0; ks < 64; ks += 8) {
                uint32_t af[4];
                ldsm4(af, QsB + 4*swz64(wq + (lm&1)*8 + lr, ks + (lm>>1)*4));
#pragma unroll
                for (int p = 0; p < 4; p++) {
                    uint32_t t[4];
                    ldsm4(t, KsB + 4*swz64(p*16 + (lm>>1)*8 + lr, ks + (lm&1)*4));
                    mma8(s[2*p],   af, t[0], t[1]);
                    mma8(s[2*p+1], af, t[2], t[3]);
                }
            }
            // mask + scale + online softmax
            float rm0=-1e30f, rm1=-1e30f;
#pragma unroll
            for (int nt = 0; nt < 8; nt++) {
                int c = c0 + nt*8 + tig*2;
                float v;
                v = (c   > r0g || c   >= Slim) ? -1e30f : s[nt][0]*0.125f; s[nt][0]=v; rm0=fmaxf(rm0,v);
                v = (c+1 > r0g || c+1 >= Slim) ? -1e30f : s[nt][1]*0.125f; s[nt][1]=v; rm0=fmaxf(rm0,v);
                v = (c   > r1g || c   >= Slim) ? -1e30f : s[nt][2]*0.125f; s[nt][2]=v; rm1=fmaxf(rm1,v);
                v = (c+1 > r1g || c+1 >= Slim) ? -1e30f : s[nt][3]*0.125f; s[nt][3]=v; rm1=fmaxf(rm1,v);
            }
            rm0 = fmaxf(rm0, __shfl_xor_sync(0xffffffffu, rm0, 1));
            rm0 = fmaxf(rm0, __shfl_xor_sync(0xffffffffu, rm0, 2));
            rm1 = fmaxf(rm1, __shfl_xor_sync(0xffffffffu, rm1, 1));
            rm1 = fmaxf(rm1, __shfl_xor_sync(0xffffffffu, rm1, 2));
            float mn0 = fmaxf(mi0, rm0), mn1 = fmaxf(mi1, rm1);
            float sc0 = __expf(mi0 - mn0), sc1 = __expf(mi1 - mn1);
            float rs0 = 0.f, rs1 = 0.f;
#pragma unroll
            for (int nt = 0; nt < 8; nt++) {
                float p00 = __expf(s[nt][0]-mn0), p01 = __expf(s[nt][1]-mn0);
                float p10 = __expf(s[nt][2]-mn1), p11 = __expf(s[nt][3]-mn1);
                rs0 += p00 + p01; rs1 += p10 + p11;
                int w = nt*8 + tig*2;
                *(float2*)&Ps[swz64(wq+g,   w)] =
                    make_float2(__uint_as_float(f2tf(p00)), __uint_as_float(f2tf(p01)));
                *(float2*)&Ps[swz64(wq+g+8, w)] =
                    make_float2(__uint_as_float(f2tf(p10)), __uint_as_float(f2tf(p11)));
                o[nt][0]*=sc0; o[nt][1]*=sc0; o[nt][2]*=sc1; o[nt][3]*=sc1;
            }
            rs0 += __shfl_xor_sync(0xffffffffu, rs0, 1);
            rs0 += __shfl_xor_sync(0xffffffffu, rs0, 2);
            rs1 += __shfl_xor_sync(0xffffffffu, rs1, 1);
            rs1 += __shfl_xor_sync(0xffffffffu, rs1, 2);
            li0 = li0*sc0 + rs0; li1 = li1*sc1 + rs1;
            mi0 = mn0; mi1 = mn1;
            __syncwarp();                    // P visible within warp

            // O += P V
#pragma unroll
            for (int cs = 0; cs < 64; cs += 8) {
                uint32_t pf[4];
                ldsm4(pf, PsB + 4*swz64(wq + (lm&1)*8 + lr, cs + (lm>>1)*4));
#pragma unroll
                for (int nt = 0; nt < 8; nt++) {
                    uint32_t b0 = __float_as_uint(Vs[(cs+tig)*72   + nt*8 + g]);
                    uint32_t b1 = __float_as_uint(Vs[(cs+tig+4)*72 + nt*8 + g]);
                    mma8(o[nt], pf, b0, b1);
                }
            }
        }
        __syncthreads();
    }

    float inv0 = 1.0f / li0, inv1 = 1.0f / li1;
#pragma unroll
    for (int nt = 0; nt < 8; nt++) {
        int col = h*64 + nt*8 + tig*2;
        // tf32 pre-round for the proj GEMM (same values as converting at its
        // smem store)
        *(float2*)&g_attn[(size_t)(b*S_ + r0g)*D_ + col] =
            make_float2(__uint_as_float(f2tf(o[nt][0]*inv0)),
                        __uint_as_float(f2tf(o[nt][1]*inv0)));
        *(float2*)&g_attn[(size_t)(b*S_ + r1g)*D_ + col] =
            make_float2(__uint_as_float(f2tf(o[nt][2]*inv1)),
                        __uint_as_float(f2tf(o[nt][3]*inv1)));
    }
}

// ---------------------------------------------------------------------------
extern "C" void kernel_launch(void* const* d_in, const int* in_sizes, int n_in,
                              void* d_out, int out_size)
{
    const float* x   = (const float*)d_in[0];
    const int*   eff = (const int*)  d_in[1];
    const float* Wq  = (const float*)d_in[2];
    const float* bq  = (const float*)d_in[3];
    const float* Wk  = (const float*)d_in[4];
    const float* bk  = (const float*)d_in[5];
    const float* Wv  = (const float*)d_in[6];
    const float* bv  = (const float*)d_in[7];
    const float* Wo  = (const float*)d_in[8];
    const float* bo  = (const float*)d_in[9];
    float* out = (float*)d_out;

    const int gemm_smem = GSTG * GTILE * 2 * (int)sizeof(float);           // 96KB
    const int attn_smem = (2*128*64 + 2*KVTILE) * (int)sizeof(float);      // ~133KB

    static bool attr_set = false;
    if (!attr_set) {
        cudaFuncSetAttribute(gemm_tc<true>,
            cudaFuncAttributeMaxDynamicSharedMemorySize, gemm_smem);
        cudaFuncSetAttribute(gemm_tc<false>,
            cudaFuncAttributeMaxDynamicSharedMemorySize, gemm_smem);
        cudaFuncSetAttribute(attn_tc,
            cudaFuncAttributeMaxDynamicSharedMemorySize, attn_smem);
        attr_set = true;
    }

    rope_table_kernel<<<(S_*32 + 255)/256, 256>>>();
    prep_kernel<<<(NXF4 + 4*NWF4 + 255)/256, 256>>>(x, Wq, Wk, Wv, Wo);

    dim3 gq(D_/128, M_TOT/128, 3);
    gemm_tc<true><<<gq, 256, gemm_smem>>>(bq, bk, bv, nullptr);

    dim3 ga(S_/128, H_, B_);
    attn_tc<<<ga, 256, attn_smem>>>(eff);

    dim3 gp(D_/128, M_TOT/128, 1);
    gemm_tc<false><<<gp, 256, gemm_smem>>>(bo, nullptr, nullptr, out);
}

// round 4
// speedup vs baseline: 4.4642x; 1.0676x over previous
#include <cuda_runtime.h>
#include <math.h>
#include <stdint.h>

#define B_  2
#define S_  2048
#define D_  1024
#define H_  16
#define M_TOT (B_*S_)

// Scratch (allocation-free: __device__ globals)
__device__ float g_x[(size_t)M_TOT*D_];   // tf32-rounded x
__device__ float g_wq[D_*D_];
__device__ float g_wk[D_*D_];
__device__ float g_wv[D_*D_];
__device__ float g_wo[D_*D_];
__device__ float g_q[B_*H_*S_*64];        // [B,H,S,64] rope'd, tf32-rounded
__device__ float g_k[B_*H_*S_*64];        // [B,H,S,64]
__device__ float g_v[B_*H_*S_*64];        // TRANSPOSED: [B,H,64,S]
__device__ float g_attn[(size_t)M_TOT*D_]; // tf32-rounded attn output
__device__ float g_cos[S_*32];
__device__ float g_sin[S_*32];

// ---------------------------------------------------------------------------
// helpers
// ---------------------------------------------------------------------------
__device__ __forceinline__ uint32_t f2tf(float x){
    uint32_t u; asm("cvt.rna.tf32.f32 %0, %1;" : "=r"(u) : "f"(x)); return u;
}
__device__ __forceinline__ float4 cvt4(float4 v){
    float4 r;
    r.x=__uint_as_float(f2tf(v.x)); r.y=__uint_as_float(f2tf(v.y));
    r.z=__uint_as_float(f2tf(v.z)); r.w=__uint_as_float(f2tf(v.w));
    return r;
}
__device__ __forceinline__ void ldsm4(uint32_t* r, uint32_t addr){
    asm volatile("ldmatrix.sync.aligned.m8n8.x4.shared.b16 {%0,%1,%2,%3}, [%4];"
        : "=r"(r[0]),"=r"(r[1]),"=r"(r[2]),"=r"(r[3]) : "r"(addr));
}
__device__ __forceinline__ void mma8(float* c, const uint32_t* a, uint32_t b0, uint32_t b1){
    asm volatile("mma.sync.aligned.m16n8k8.row.col.f32.tf32.tf32.f32 "
        "{%0,%1,%2,%3},{%4,%5,%6,%7},{%8,%9},{%0,%1,%2,%3};"
        : "+f"(c[0]),"+f"(c[1]),"+f"(c[2]),"+f"(c[3])
        : "r"(a[0]),"r"(a[1]),"r"(a[2]),"r"(a[3]),"r"(b0),"r"(b1));
}
__device__ __forceinline__ void cpa16(uint32_t dst, const float* src){
    asm volatile("cp.async.cg.shared.global [%0], [%1], 16;" :: "r"(dst), "l"(src));
}
#define CP_COMMIT() asm volatile("cp.async.commit_group;")
#define CP_WAIT(n)  asm volatile("cp.async.wait_group %0;"::"n"(n))

// XOR-swizzled [row][word] layouts (16B-chunk swizzle; conflict-free LDSM)
__device__ __forceinline__ int swz32(int r,int w){ return r*32 + ((((w>>2)^(r&7))<<2)|(w&3)); }
__device__ __forceinline__ int swz64(int r,int w){ return r*64 + ((((w>>2)^(r&7))<<2)|(w&3)); }

// ---------------------------------------------------------------------------
// RoPE tables (match numpy fp32 pipeline)
// ---------------------------------------------------------------------------
__global__ void rope_table_kernel() {
    int idx = blockIdx.x * blockDim.x + threadIdx.x;
    if (idx >= S_ * 32) return;
    int p = idx & 31;
    int t = idx >> 5;
    double inv = exp(-log(10000.0) * ((double)(2 * p) / 64.0));
    float ang = (float)t * (float)inv;
    g_cos[idx] = cosf(ang);
    g_sin[idx] = sinf(ang);
}

// ---------------------------------------------------------------------------
// prep: tf32-round x and the four weight matrices into device scratch
// ---------------------------------------------------------------------------
#define NXF4 ((M_TOT*D_)/4)
#define NWF4 ((D_*D_)/4)
__global__ void prep_kernel(const float* __restrict__ x,
                            const float* __restrict__ Wq, const float* __restrict__ Wk,
                            const float* __restrict__ Wv, const float* __restrict__ Wo)
{
    int i = blockIdx.x * blockDim.x + threadIdx.x;
    if (i < NXF4) { ((float4*)g_x)[i] = cvt4(((const float4*)x)[i]); return; }
    i -= NXF4;
    if (i < NWF4) { ((float4*)g_wq)[i] = cvt4(((const float4*)Wq)[i]); return; }
    i -= NWF4;
    if (i < NWF4) { ((float4*)g_wk)[i] = cvt4(((const float4*)Wk)[i]); return; }
    i -= NWF4;
    if (i < NWF4) { ((float4*)g_wv)[i] = cvt4(((const float4*)Wv)[i]); return; }
    i -= NWF4;
    if (i < NWF4) { ((float4*)g_wo)[i] = cvt4(((const float4*)Wo)[i]); return; }
}

// ---------------------------------------------------------------------------
// TF32 tensor-core GEMM, cp.async 3-stage pipeline.
// Y = A @ W^T + b. Block 128x128, BK=32, 256 threads, warp tile 64x32.
// ---------------------------------------------------------------------------
#define GSTG 3
#define GTILE (128*32)

template<bool IS_QKV>
__global__ __launch_bounds__(256,2) void gemm_tc(
    const float* __restrict__ bq, const float* __restrict__ bk,
    const float* __restrict__ bv, float* __restrict__ outp)
{
    extern __shared__ float sm[];
    float* As = sm;                 // [GSTG][128*32]
    float* Bs = sm + GSTG*GTILE;

    const float* A; const float* W; const float* bias; float* out;
    int which = 0;
    if (IS_QKV) {
        which = blockIdx.z;
        A = g_x;
        W    = (which==0) ? g_wq : (which==1) ? g_wk : g_wv;
        bias = (which==0) ? bq   : (which==1) ? bk   : bv;
        out  = (which==0) ? g_q  : (which==1) ? g_k  : g_v;
    } else {
        A = g_attn; W = g_wo; bias = bq; out = outp;
    }

    int tid = threadIdx.x, lane = tid & 31, warp = tid >> 5;
    int wm = (warp & 1) * 64, wn = (warp >> 1) * 32;
    int lm = lane >> 3, lr = lane & 7;
    int row0 = blockIdx.y * 128, col0 = blockIdx.x * 128;

    uint32_t aB = (uint32_t)__cvta_generic_to_shared(As);
    uint32_t bB = (uint32_t)__cvta_generic_to_shared(Bs);

    int ldr = tid >> 3;          // 0..31
    int ldc = (tid & 7) * 4;     // word
    int swo = swz32(ldr, ldc);
    const float* aP = A + (size_t)(row0 + ldr) * D_ + ldc;
    const float* bP = W + (size_t)(col0 + ldr) * D_ + ldc;

    float acc[4][4][4];
#pragma unroll
    for (int i=0;i<4;i++)
#pragma unroll
        for (int j=0;j<4;j++)
#pragma unroll
            for (int k=0;k<4;k++) acc[i][j][k]=0.f;

    const int NT = D_/32;

#pragma unroll
    for (int s = 0; s < GSTG; s++) {
        uint32_t ab = aB + (uint32_t)(s*GTILE*4);
        uint32_t bb = bB + (uint32_t)(s*GTILE*4);
        int k0 = s*32;
#pragma unroll
        for (int it = 0; it < 4; it++) {
            cpa16(ab + 4*(swo + it*32*32), aP + (size_t)it*32*D_ + k0);
            cpa16(bb + 4*(swo + it*32*32), bP + (size_t)it*32*D_ + k0);
        }
        CP_COMMIT();
    }

    for (int kt = 0; kt < NT; kt++) {
        CP_WAIT(2);
        __syncthreads();

        int buf = kt % GSTG;
        uint32_t ab = aB + (uint32_t)(buf*GTILE*4);
        uint32_t bb = bB + (uint32_t)(buf*GTILE*4);
#pragma unroll
        for (int ks = 0; ks < 32; ks += 8) {
            uint32_t af[4][4];
#pragma unroll
            for (int mt = 0; mt < 4; mt++)
                ldsm4(af[mt], ab + 4*swz32(wm + mt*16 + (lm&1)*8 + lr, ks + (lm>>1)*4));
            uint32_t bf[4][2];
#pragma unroll
            for (int p = 0; p < 2; p++) {
                uint32_t t[4];
                ldsm4(t, bb + 4*swz32(wn + p*16 + (lm>>1)*8 + lr, ks + (lm&1)*4));
                bf[2*p][0]=t[0]; bf[2*p][1]=t[1]; bf[2*p+1][0]=t[2]; bf[2*p+1][1]=t[3];
            }
#pragma unroll
            for (int mt = 0; mt < 4; mt++)
#pragma unroll
                for (int nt = 0; nt < 4; nt++)
                    mma8(acc[mt][nt], af[mt], bf[nt][0], bf[nt][1]);
        }
        __syncthreads();

        if (kt + GSTG < NT) {
            int k0 = (kt + GSTG)*32;
#pragma unroll
            for (int it = 0; it < 4; it++) {
                cpa16(ab + 4*(swo + it*32*32), aP + (size_t)it*32*D_ + k0);
                cpa16(bb + 4*(swo + it*32*32), bP + (size_t)it*32*D_ + k0);
            }
        }
        CP_COMMIT();
    }

    int g = lane >> 2, tig = lane & 3;
#pragma unroll
    for (int mt = 0; mt < 4; mt++) {
#pragma unroll
        for (int nt = 0; nt < 4; nt++) {
            int ncol = col0 + wn + nt*8 + tig*2;
            float b0 = bias[ncol], b1 = bias[ncol+1];
#pragma unroll
            for (int h2 = 0; h2 < 2; h2++) {
                int m = row0 + wm + mt*16 + g + h2*8;
                float v0 = acc[mt][nt][h2*2]   + b0;
                float v1 = acc[mt][nt][h2*2+1] + b1;
                if (IS_QKV) {
                    int s_ = m & (S_-1);
                    int hh = ncol >> 6, d0 = ncol & 63;
                    if (which < 2) {
                        int p = d0 >> 1;
                        float c = g_cos[s_*32+p], sn = g_sin[s_*32+p];
                        float o0 = v0*c - v1*sn;
                        float o1 = v0*sn + v1*c;
                        v0 = o0; v1 = o1;
                    }
                    v0 = __uint_as_float(f2tf(v0));
                    v1 = __uint_as_float(f2tf(v1));
                    int bb_ = m >> 11;
                    if (which == 2) {
                        // V transposed: [B,H,64,S]
                        float* op = out + (((size_t)(bb_*H_ + hh)*64 + d0)*S_ + s_);
                        op[0]  = v0;
                        op[S_] = v1;
                    } else {
                        float2* op = (float2*)(out + (((size_t)(bb_*H_ + hh)*S_ + s_)<<6) + d0);
                        *op = make_float2(v0, v1);
                    }
                } else {
                    float2* op = (float2*)(out + (size_t)m*D_ + ncol);
                    *op = make_float2(v0, v1);
                }
            }
        }
    }
}

// ---------------------------------------------------------------------------
// TF32 flash attention: q-tile 64, k-tile 64, 128 threads (4 warps x 16 rows),
// 2 CTAs/SM. V transposed in smem -> ldmatrix B-fragments. Base-2 softmax
// with interior-tile fast path. cp.async double-buffered K/V.
// ---------------------------------------------------------------------------
#define KVSTG (64*64*2)          // Ks(swz64) + Vt(swz64) per stage, floats
#define ASM_FLOATS (2*64*64 + 2*KVSTG)

__global__ __launch_bounds__(128,2) void attn_tc(const int* __restrict__ eff)
{
    extern __shared__ float sm[];
    float* Qs  = sm;                       // swz64, 64x64
    float* Ps  = sm + 64*64;               // swz64, 64x64
    float* KV0 = sm + 2*64*64;             // [2] stages: Ks(64x64) + Vt(64x64)

    const float SC = 0.125f * 1.44269504088896340736f;   // /sqrt(64) * log2(e)

    int tid = threadIdx.x, lane = tid & 31, warp = tid >> 5;
    int g = lane >> 2, tig = lane & 3, lm = lane >> 3, lr = lane & 7;
    int qt = (int)gridDim.x - 1 - (int)blockIdx.x;       // heavy CTAs first
    int q0 = qt * 64, h = blockIdx.y, b = blockIdx.z;
    int wq = warp * 16;

    const float* qb  = g_q + (((size_t)(b*H_+h)*S_ + q0) << 6);
    const float* kb  = g_k + (((size_t)(b*H_+h)*S_) << 6);
    const float* vtb = g_v + ((size_t)(b*H_+h)*64) * S_;  // [64][S]

    uint32_t QsB = (uint32_t)__cvta_generic_to_shared(Qs);
    uint32_t PsB = (uint32_t)__cvta_generic_to_shared(Ps);
    uint32_t KVB = (uint32_t)__cvta_generic_to_shared(KV0);

    int lrow = tid >> 4;         // 0..7
    int lcol = (tid & 15) * 4;   // word

    int Slim = S_ - eff[b];
    int kend = min(q0 + 64, Slim);
    int nkt = (kend + 63) >> 6;

    // group 0: Q tile + KV tile 0
#pragma unroll
    for (int it = 0; it < 8; it++) {
        int r = it*8 + lrow;
        cpa16(QsB + 4*swz64(r, lcol), qb + r*64 + lcol);
    }
#pragma unroll
    for (int it = 0; it < 8; it++) {
        int r = it*8 + lrow;
        cpa16(KVB + 4*swz64(r, lcol),            kb  + (size_t)r*64 + lcol);
        cpa16(KVB + 4*(64*64 + swz64(r, lcol)),  vtb + (size_t)r*S_ + lcol);
    }
    CP_COMMIT();

    float o[8][4];
#pragma unroll
    for (int i=0;i<8;i++)
#pragma unroll
        for (int j=0;j<4;j++) o[i][j]=0.f;
    float mi0=-1e30f, mi1=-1e30f, li0=0.f, li1=0.f;

    int r0g = q0 + wq + g;
    int r1g = r0g + 8;

    for (int kt = 0; kt < nkt; kt++) {
        if (kt + 1 < nkt) {
            uint32_t kvb = KVB + (uint32_t)(((kt+1)&1) * KVSTG * 4);
            int c0n = (kt+1) * 64;
#pragma unroll
            for (int it = 0; it < 8; it++) {
                int r = it*8 + lrow;
                cpa16(kvb + 4*swz64(r, lcol),           kb  + (size_t)(c0n+r)*64 + lcol);
                cpa16(kvb + 4*(64*64 + swz64(r, lcol)), vtb + (size_t)r*S_ + c0n + lcol);
            }
        }
        CP_COMMIT();
        CP_WAIT(1);
        __syncthreads();

        int c0 = kt * 64;
        uint32_t KsB = KVB + (uint32_t)((kt&1) * KVSTG * 4);
        uint32_t VtB = KsB + 4*64*64;

        if (c0 <= q0 + wq + 15) {            // causal: skip fully-masked tiles
            // S = Q K^T
            float s[8][4];
#pragma unroll
            for (int i=0;i<8;i++)
#pragma unroll
                for (int j=0;j<4;j++) s[i][j]=0.f;
#pragma unroll
            for (int ks = 0; ks < 64; ks += 8) {
                uint32_t af[4];
                ldsm4(af, QsB + 4*swz64(wq + (lm&1)*8 + lr, ks + (lm>>1)*4));
#pragma unroll
                for (int p = 0; p < 4; p++) {
                    uint32_t t[4];
                    ldsm4(t, KsB + 4*swz64(p*16 + (lm>>1)*8 + lr, ks + (lm&1)*4));
                    mma8(s[2*p],   af, t[0], t[1]);
                    mma8(s[2*p+1], af, t[2], t[3]);
                }
            }

            // scale (+mask only on edge tiles), row max — base-2 domain
            float rm0=-1e30f, rm1=-1e30f;
            bool edge = (c0 + 63 > q0 + wq) || (c0 + 64 > Slim);
            if (edge) {
#pragma unroll
                for (int nt = 0; nt < 8; nt++) {
                    int c = c0 + nt*8 + tig*2;
                    float v;
                    v = (c   > r0g || c   >= Slim) ? -1e30f : s[nt][0]*SC; s[nt][0]=v; rm0=fmaxf(rm0,v);
                    v = (c+1 > r0g || c+1 >= Slim) ? -1e30f : s[nt][1]*SC; s[nt][1]=v; rm0=fmaxf(rm0,v);
                    v = (c   > r1g || c   >= Slim) ? -1e30f : s[nt][2]*SC; s[nt][2]=v; rm1=fmaxf(rm1,v);
                    v = (c+1 > r1g || c+1 >= Slim) ? -1e30f : s[nt][3]*SC; s[nt][3]=v; rm1=fmaxf(rm1,v);
                }
            } else {
#pragma unroll
                for (int nt = 0; nt < 8; nt++) {
                    s[nt][0]*=SC; rm0=fmaxf(rm0,s[nt][0]);
                    s[nt][1]*=SC; rm0=fmaxf(rm0,s[nt][1]);
                    s[nt][2]*=SC; rm1=fmaxf(rm1,s[nt][2]);
                    s[nt][3]*=SC; rm1=fmaxf(rm1,s[nt][3]);
                }
            }
            rm0 = fmaxf(rm0, __shfl_xor_sync(0xffffffffu, rm0, 1));
            rm0 = fmaxf(rm0, __shfl_xor_sync(0xffffffffu, rm0, 2));
            rm1 = fmaxf(rm1, __shfl_xor_sync(0xffffffffu, rm1, 1));
            rm1 = fmaxf(rm1, __shfl_xor_sync(0xffffffffu, rm1, 2));
            float mn0 = fmaxf(mi0, rm0), mn1 = fmaxf(mi1, rm1);
            float sc0 = exp2f(mi0 - mn0), sc1 = exp2f(mi1 - mn1);
            float rs0 = 0.f, rs1 = 0.f;
#pragma unroll
            for (int nt = 0; nt < 8; nt++) {
                float p00 = exp2f(s[nt][0]-mn0), p01 = exp2f(s[nt][1]-mn0);
                float p10 = exp2f(s[nt][2]-mn1), p11 = exp2f(s[nt][3]-mn1);
                rs0 += p00 + p01; rs1 += p10 + p11;
                int w = nt*8 + tig*2;
                *(float2*)&Ps[swz64(wq+g,   w)] =
                    make_float2(__uint_as_float(f2tf(p00)), __uint_as_float(f2tf(p01)));
                *(float2*)&Ps[swz64(wq+g+8, w)] =
                    make_float2(__uint_as_float(f2tf(p10)), __uint_as_float(f2tf(p11)));
                o[nt][0]*=sc0; o[nt][1]*=sc0; o[nt][2]*=sc1; o[nt][3]*=sc1;
            }
            rs0 += __shfl_xor_sync(0xffffffffu, rs0, 1);
            rs0 += __shfl_xor_sync(0xffffffffu, rs0, 2);
            rs1 += __shfl_xor_sync(0xffffffffu, rs1, 1);
            rs1 += __shfl_xor_sync(0xffffffffu, rs1, 2);
            li0 = li0*sc0 + rs0; li1 = li1*sc1 + rs1;
            mi0 = mn0; mi1 = mn1;
            __syncwarp();                    // P visible within warp

            // O += P V  (V fragments via ldmatrix from transposed Vt)
            int part = lane >> 3, j = lane & 7;
#pragma unroll
            for (int cs = 0; cs < 64; cs += 8) {
                uint32_t pf[4];
                ldsm4(pf, PsB + 4*swz64(wq + (lm&1)*8 + lr, cs + (lm>>1)*4));
#pragma unroll
                for (int dp = 0; dp < 4; dp++) {
                    int d = dp*16 + ((part&2)?8:0) + j;
                    int c = cs + ((part&1)?4:0);
                    uint32_t t[4];
                    ldsm4(t, VtB + 4*swz64(d, c));
                    mma8(o[2*dp],   pf, t[0], t[1]);
                    mma8(o[2*dp+1], pf, t[2], t[3]);
                }
            }
        }
        __syncthreads();
    }

    float inv0 = 1.0f / li0, inv1 = 1.0f / li1;
#pragma unroll
    for (int nt = 0; nt < 8; nt++) {
        int col = h*64 + nt*8 + tig*2;
        *(float2*)&g_attn[(size_t)(b*S_ + r0g)*D_ + col] =
            make_float2(__uint_as_float(f2tf(o[nt][0]*inv0)),
                        __uint_as_float(f2tf(o[nt][1]*inv0)));
        *(float2*)&g_attn[(size_t)(b*S_ + r1g)*D_ + col] =
            make_float2(__uint_as_float(f2tf(o[nt][2]*inv1)),
                        __uint_as_float(f2tf(o[nt][3]*inv1)));
    }
}

// ---------------------------------------------------------------------------
extern "C" void kernel_launch(void* const* d_in, const int* in_sizes, int n_in,
                              void* d_out, int out_size)
{
    const float* x   = (const float*)d_in[0];
    const int*   eff = (const int*)  d_in[1];
    const float* bq  = (const float*)d_in[3];
    const float* Wq  = (const float*)d_in[2];
    const float* Wk  = (const float*)d_in[4];
    const float* bk  = (const float*)d_in[5];
    const float* Wv  = (const float*)d_in[6];
    const float* bv  = (const float*)d_in[7];
    const float* Wo  = (const float*)d_in[8];
    const float* bo  = (const float*)d_in[9];
    float* out = (float*)d_out;

    const int gemm_smem = GSTG * GTILE * 2 * (int)sizeof(float);   // 96KB
    const int attn_smem = ASM_FLOATS * (int)sizeof(float);         // 96KB

    static bool attr_set = false;
    if (!attr_set) {
        cudaFuncSetAttribute(gemm_tc<true>,
            cudaFuncAttributeMaxDynamicSharedMemorySize, gemm_smem);
        cudaFuncSetAttribute(gemm_tc<false>,
            cudaFuncAttributeMaxDynamicSharedMemorySize, gemm_smem);
        cudaFuncSetAttribute(attn_tc,
            cudaFuncAttributeMaxDynamicSharedMemorySize, attn_smem);
        attr_set = true;
    }

    rope_table_kernel<<<(S_*32 + 255)/256, 256>>>();
    prep_kernel<<<(NXF4 + 4*NWF4 + 255)/256, 256>>>(x, Wq, Wk, Wv, Wo);

    dim3 gq(D_/128, M_TOT/128, 3);
    gemm_tc<true><<<gq, 256, gemm_smem>>>(bq, bk, bv, nullptr);

    dim3 ga(S_/64, H_, B_);
    attn_tc<<<ga, 128, attn_smem>>>(eff);

    dim3 gp(D_/128, M_TOT/128, 1);
    gemm_tc<false><<<gp, 256, gemm_smem>>>(bo, nullptr, nullptr, out);
}